// round 10
// baseline (speedup 1.0000x reference)
#include <cuda_runtime.h>
#include <cuda_bf16.h>
#include <cstdint>

#define U_   32768
#define EPSF 1e-6f

// ---------------- scratch globals ----------------
__device__ int   g_count;
__device__ int   g_idx[U_];
__device__ float g_mean1[U_], g_rstd1[U_];          // compacted
__device__ float g_sum2[U_], g_sumsq2[U_];          // compacted
__device__ float g_h1[(size_t)U_ * 512];            // compacted rows
__device__ float g_grid[64 * 64 * 256];
__device__ __nv_bfloat16 g_gh[64 * 64 * 256], g_gl[64 * 64 * 256];
__device__ __nv_bfloat16 g_w1h[512 * 512], g_w1l[512 * 512];       // [n][k]
__device__ __nv_bfloat16 g_w2h[256 * 512], g_w2l[256 * 512];       // [n][k]
__device__ __nv_bfloat16 g_wch[9 * 256 * 256], g_wcl[9 * 256 * 256]; // [tap][co][ci]

// ---------------- helpers ----------------
__device__ __forceinline__ uint32_t smem_u32(const void* p) {
    uint32_t a;
    asm("{ .reg .u64 t; cvta.to.shared.u64 t, %1; cvt.u32.u64 %0, t; }" : "=r"(a) : "l"(p));
    return a;
}
__device__ __forceinline__ void cpa16(uint32_t d, const void* s) {
    asm volatile("cp.async.cg.shared.global [%0], [%1], 16;" :: "r"(d), "l"(s));
}
__device__ __forceinline__ void cpa16z(uint32_t d, const void* s, int sz) {
    asm volatile("cp.async.ca.shared.global [%0], [%1], 16, %2;" :: "r"(d), "l"(s), "r"(sz));
}
__device__ __forceinline__ void cpa_commit() { asm volatile("cp.async.commit_group;" ::: "memory"); }
__device__ __forceinline__ void cpa_wait0()  { asm volatile("cp.async.wait_group 0;"  ::: "memory"); }
__device__ __forceinline__ void ldx4(uint32_t* r, uint32_t a) {
    asm volatile("ldmatrix.sync.aligned.m8n8.x4.shared.b16 {%0,%1,%2,%3}, [%4];"
                 : "=r"(r[0]), "=r"(r[1]), "=r"(r[2]), "=r"(r[3]) : "r"(a));
}
__device__ __forceinline__ void mma_bf16(float* c, const uint32_t* a, const uint32_t* b) {
    asm volatile(
        "mma.sync.aligned.m16n8k16.row.col.f32.bf16.bf16.f32 "
        "{%0,%1,%2,%3}, {%4,%5,%6,%7}, {%8,%9}, {%0,%1,%2,%3};"
        : "+f"(c[0]), "+f"(c[1]), "+f"(c[2]), "+f"(c[3])
        : "r"(a[0]), "r"(a[1]), "r"(a[2]), "r"(a[3]), "r"(b[0]), "r"(b[1]));
}
__device__ __forceinline__ void bsplit(float v, __nv_bfloat16& h, __nv_bfloat16& l) {
    h = __float2bfloat16(v);
    l = __float2bfloat16(v - __bfloat162float(h));
}

// ---------------- fused setup ----------------
__global__ void setup_kernel(const float* __restrict__ W1, const float* __restrict__ W2,
                             const float* __restrict__ cw) {
    int b = blockIdx.x, t = threadIdx.x;
    if (b < 1024) {
        ((float4*)g_grid)[b * 256 + t] = make_float4(0, 0, 0, 0);
    } else if (b < 1088) {
        int i = (b - 1024) * 256 + t;
        if (i < 8192) ((float4*)g_sum2)[i] = make_float4(0, 0, 0, 0);
        else ((float4*)g_sumsq2)[i - 8192] = make_float4(0, 0, 0, 0);
    } else if (b < 1120) {
        ((int4*)g_idx)[(b - 1088) * 256 + t] = make_int4(0, 0, 0, 0);
    } else if (b < 1121) {
        if (t == 0) g_count = 0;
    } else if (b < 2145) {
        int i = (b - 1121) * 256 + t;
        int n = i >> 9, k = i & 511;
        bsplit(W1[(size_t)k * 512 + n], g_w1h[(size_t)n * 512 + k], g_w1l[(size_t)n * 512 + k]);
    } else if (b < 2657) {
        int i = (b - 2145) * 256 + t;
        int n = i >> 9, k = i & 511;
        bsplit(W2[(size_t)k * 256 + n], g_w2h[(size_t)n * 512 + k], g_w2l[(size_t)n * 512 + k]);
    } else {
        int i = (b - 2657) * 256 + t;
        int tap = i >> 16, r = i & 65535, co = r >> 8, ci = r & 255;
        bsplit(cw[((size_t)tap * 256 + ci) * 256 + co],
               g_wch[(size_t)tap * 65536 + co * 256 + ci],
               g_wcl[(size_t)tap * 65536 + co * 256 + ci]);
    }
}

// ---------------- compaction + LN1 stats ----------------
__global__ void compact_stats_kernel(const float* __restrict__ z, const int* __restrict__ ne) {
    int row = blockIdx.x;
    if (ne[row] == 0) return;
    __shared__ int spos;
    if (threadIdx.x == 0) spos = atomicAdd(&g_count, 1);
    const float4* xr = (const float4*)(z + (size_t)row * 512);
    float s, q;
    {
        float4 v = xr[threadIdx.x];
        s = v.x + v.y + v.z + v.w;
        q = v.x * v.x + v.y * v.y + v.z * v.z + v.w * v.w;
    }
#pragma unroll
    for (int o = 16; o > 0; o >>= 1) {
        s += __shfl_down_sync(~0u, s, o); q += __shfl_down_sync(~0u, q, o);
    }
    __shared__ float ws[4], wq[4];
    if ((threadIdx.x & 31) == 0) { ws[threadIdx.x >> 5] = s; wq[threadIdx.x >> 5] = q; }
    __syncthreads();
    if (threadIdx.x == 0) {
        int pos = spos;
        s = ws[0] + ws[1] + ws[2] + ws[3]; q = wq[0] + wq[1] + wq[2] + wq[3];
        float m = s / 512.f, v = q / 512.f - m * m;
        g_idx[pos] = row;
        g_mean1[pos] = m; g_rstd1[pos] = rsqrtf(v + EPSF);
    }
}

// ---------------- tiles: M=64, N=128, BK=64; 128 threads, 4 warps (2Mx2N, warp 32x64) ----------------
#define PBY 144
#define T_SA (64 * PBY)
#define T_AH 0
#define T_AL T_SA
#define T_BH (2 * T_SA)
#define T_SB (128 * PBY)
#define T_BL (2 * T_SA + T_SB)
#define T_STG (2 * T_SA + 2 * T_SB)
#define T_SMEM (2 * T_STG)
#define G_NCH 8
#define C_NCH 36

// LN + relu + split of 32 contiguous values, stored to smem (hi/lo)
__device__ __forceinline__ void lnsplit_store32(const float* va, float mA, float rsA,
        const float* __restrict__ lnS, const float* __restrict__ lnB, int kb,
        uint32_t dAH, uint32_t dAL) {
    uint32_t hi[16], lo[16];
#pragma unroll
    for (int e = 0; e < 16; e++) {
        float a0 = fmaxf((va[2*e]   - mA) * rsA * __ldg(lnS + kb + 2*e)     + __ldg(lnB + kb + 2*e),     0.f);
        float a1 = fmaxf((va[2*e+1] - mA) * rsA * __ldg(lnS + kb + 2*e + 1) + __ldg(lnB + kb + 2*e + 1), 0.f);
        __nv_bfloat162 H, L;
        bsplit(a0, H.x, L.x); bsplit(a1, H.y, L.y);
        hi[e] = *(uint32_t*)&H; lo[e] = *(uint32_t*)&L;
    }
#pragma unroll
    for (int v = 0; v < 4; v++) {
        asm volatile("st.shared.v4.b32 [%0], {%1,%2,%3,%4};"
                     :: "r"(dAH + v * 16), "r"(hi[4*v]), "r"(hi[4*v+1]), "r"(hi[4*v+2]), "r"(hi[4*v+3]));
        asm volatile("st.shared.v4.b32 [%0], {%1,%2,%3,%4};"
                     :: "r"(dAL + v * 16), "r"(lo[4*v]), "r"(lo[4*v+1]), "r"(lo[4*v+2]), "r"(lo[4*v+3]));
    }
}

// Warp tile 32x64: A frags 2, B frags 4 (n16 each). 3 passes of 16 independent MMAs.
#define MMA_K16W(curB, AHOFF, ALOFF, BHOFF, BLOFF)                                             \
    {                                                                                          \
        uint32_t ah[2][4], al[2][4], bh[4][4], bl[4][4];                                       \
        _Pragma("unroll")                                                                      \
        for (int i = 0; i < 2; i++) {                                                          \
            uint32_t ra = (uint32_t)(wm + i * 16 + lr8 + (lg & 1) * 8) * PBY                   \
                        + (k0 + (lg >> 1) * 8) * 2;                                            \
            ldx4(ah[i], (curB) + (AHOFF) + ra);                                                \
            ldx4(al[i], (curB) + (ALOFF) + ra);                                                \
        }                                                                                      \
        _Pragma("unroll")                                                                      \
        for (int j = 0; j < 4; j++) {                                                          \
            uint32_t rb = (uint32_t)(wn + j * 16 + lr8 + (lg >> 1) * 8) * PBY                  \
                        + (k0 + (lg & 1) * 8) * 2;                                             \
            ldx4(bh[j], (curB) + (BHOFF) + rb);                                                \
            ldx4(bl[j], (curB) + (BLOFF) + rb);                                                \
        }                                                                                      \
        _Pragma("unroll")                                                                      \
        for (int i = 0; i < 2; i++)                                                            \
            _Pragma("unroll")                                                                  \
            for (int j = 0; j < 4; j++) {                                                      \
                mma_bf16(acc[i][2*j],     ah[i], bh[j]);                                       \
                mma_bf16(acc[i][2*j + 1], ah[i], bh[j] + 2);                                   \
            }                                                                                  \
        _Pragma("unroll")                                                                      \
        for (int i = 0; i < 2; i++)                                                            \
            _Pragma("unroll")                                                                  \
            for (int j = 0; j < 4; j++) {                                                      \
                mma_bf16(acc[i][2*j],     al[i], bh[j]);                                       \
                mma_bf16(acc[i][2*j + 1], al[i], bh[j] + 2);                                   \
            }                                                                                  \
        _Pragma("unroll")                                                                      \
        for (int i = 0; i < 2; i++)                                                            \
            _Pragma("unroll")                                                                  \
            for (int j = 0; j < 4; j++) {                                                      \
                mma_bf16(acc[i][2*j],     ah[i], bl[j]);                                       \
                mma_bf16(acc[i][2*j + 1], ah[i], bl[j] + 2);                                   \
            }                                                                                  \
    }

template <int MODE>
__global__ void __launch_bounds__(128, 2)
gemm_mma(const float* __restrict__ zin,
         const float* __restrict__ lnS, const float* __restrict__ lnB,
         const float* __restrict__ bias,
         const int* __restrict__ ux, const int* __restrict__ uy) {
    int cnt = g_count;
    int cntPad = (cnt + 63) & ~63;
    int rowBase = blockIdx.y * 64;
    if (rowBase >= cntPad) return;

    extern __shared__ char smv[];
    uint32_t sb = smem_u32(smv);
    int tid = threadIdx.x, wid = tid >> 5, lane = tid & 31;
    int nBase = blockIdx.x * 128;
    const __nv_bfloat16* WhP = (MODE == 0) ? g_w1h : g_w2h;
    const __nv_bfloat16* WlP = (MODE == 0) ? g_w1l : g_w2l;

    // A producer: thread -> (row, 32-float half-row)
    int arow = tid >> 1, half = tid & 1;
    int gr = rowBase + arow;
    const float* Arow;
    float mA, rsA;
    if (MODE == 0) {
        mA = g_mean1[gr]; rsA = g_rstd1[gr];
        Arow = zin + (size_t)g_idx[gr] * 512;
    } else {
        float s = g_sum2[gr] * (1.f / 512.f), qq = g_sumsq2[gr] * (1.f / 512.f);
        mA = s; rsA = rsqrtf(qq - s * s + EPSF);
        Arow = g_h1 + (size_t)gr * 512;
    }
    uint32_t dA = arow * PBY + half * 64;
    // B producer: thread -> one full n row (128B per chunk per buffer)
    int bn = tid;
    const char* srcBH = (const char*)(WhP + (size_t)(nBase + bn) * 512);
    const char* srcBL = (const char*)(WlP + (size_t)(nBase + bn) * 512);
    uint32_t dB = bn * PBY;

    float acc[2][8][4];
#pragma unroll
    for (int i = 0; i < 2; i++)
#pragma unroll
        for (int j = 0; j < 8; j++)
#pragma unroll
            for (int e = 0; e < 4; e++) acc[i][j][e] = 0.f;

    int wm = (wid >> 1) * 32, wn = (wid & 1) * 64;
    int lg = lane >> 3, lr8 = lane & 7;
    float va[32];

    // prologue: chunk 0 -> stage 0
    {
        const float4* s4 = (const float4*)(Arow + half * 32);
#pragma unroll
        for (int i2 = 0; i2 < 8; i2++) ((float4*)va)[i2] = s4[i2];
#pragma unroll
        for (int j2 = 0; j2 < 8; j2++) {
            cpa16(sb + T_BH + dB + j2 * 16, srcBH + j2 * 16);
            cpa16(sb + T_BL + dB + j2 * 16, srcBL + j2 * 16);
        }
        lnsplit_store32(va, mA, rsA, lnS, lnB, half * 32, sb + T_AH + dA, sb + T_AL + dA);
        cpa_commit(); cpa_wait0(); __syncthreads();
    }

    for (int c = 0; c < G_NCH; c++) {
        int cur = c & 1;
        uint32_t curB = sb + cur * T_STG, nxtB = sb + (cur ^ 1) * T_STG;
        if (c + 1 < G_NCH) {
#pragma unroll
            for (int j2 = 0; j2 < 8; j2++) {
                cpa16(nxtB + T_BH + dB + j2 * 16, srcBH + (c + 1) * 128 + j2 * 16);
                cpa16(nxtB + T_BL + dB + j2 * 16, srcBL + (c + 1) * 128 + j2 * 16);
            }
            const float4* s4 = (const float4*)(Arow + (c + 1) * 64 + half * 32);
#pragma unroll
            for (int i2 = 0; i2 < 8; i2++) ((float4*)va)[i2] = s4[i2];
        }
#pragma unroll
        for (int ks = 0; ks < 4; ks++) {
            int k0 = ks * 16;
            MMA_K16W(curB, T_AH, T_AL, T_BH, T_BL)
        }
        if (c + 1 < G_NCH)
            lnsplit_store32(va, mA, rsA, lnS, lnB, (c + 1) * 64 + half * 32,
                            nxtB + T_AH + dA, nxtB + T_AL + dA);
        cpa_commit(); cpa_wait0(); __syncthreads();
    }

    // ---- epilogue ----
    int elr = lane >> 2, elc = (lane & 3) * 2;
#pragma unroll
    for (int i = 0; i < 2; i++) {
        int r0 = rowBase + wm + i * 16 + elr;
        int r1 = r0 + 8;
        if (MODE == 0) {
            float s0 = 0, q0 = 0, s1 = 0, q1 = 0;
#pragma unroll
            for (int jt = 0; jt < 8; jt++) {
                int col = nBase + wn + jt * 8 + elc;
                float b0 = __ldg(bias + col), b1 = __ldg(bias + col + 1);
                float d0 = acc[i][jt][0] + b0, d1 = acc[i][jt][1] + b1;
                float d2 = acc[i][jt][2] + b0, d3 = acc[i][jt][3] + b1;
                *(float2*)(g_h1 + (size_t)r0 * 512 + col) = make_float2(d0, d1);
                *(float2*)(g_h1 + (size_t)r1 * 512 + col) = make_float2(d2, d3);
                s0 += d0 + d1; q0 += d0 * d0 + d1 * d1;
                s1 += d2 + d3; q1 += d2 * d2 + d3 * d3;
            }
#pragma unroll
            for (int o = 1; o < 4; o <<= 1) {
                s0 += __shfl_xor_sync(~0u, s0, o); q0 += __shfl_xor_sync(~0u, q0, o);
                s1 += __shfl_xor_sync(~0u, s1, o); q1 += __shfl_xor_sync(~0u, q1, o);
            }
            if ((lane & 3) == 0) {
                atomicAdd(&g_sum2[r0], s0); atomicAdd(&g_sumsq2[r0], q0);
                atomicAdd(&g_sum2[r1], s1); atomicAdd(&g_sumsq2[r1], q1);
            }
        } else {
            int c0 = -1, c1 = -1;
            if (r0 < cnt) { int o0 = g_idx[r0]; c0 = (uy[o0] * 64 + ux[o0]) * 256; }
            if (r1 < cnt) { int o1 = g_idx[r1]; c1 = (uy[o1] * 64 + ux[o1]) * 256; }
#pragma unroll
            for (int jt = 0; jt < 8; jt++) {
                int col = nBase + wn + jt * 8 + elc;
                float b0 = __ldg(bias + col), b1 = __ldg(bias + col + 1);
                if (c0 >= 0) {
                    atomicAdd(&g_grid[c0 + col],     acc[i][jt][0] + b0);
                    atomicAdd(&g_grid[c0 + col + 1], acc[i][jt][1] + b1);
                }
                if (c1 >= 0) {
                    atomicAdd(&g_grid[c1 + col],     acc[i][jt][2] + b0);
                    atomicAdd(&g_grid[c1 + col + 1], acc[i][jt][3] + b1);
                }
            }
        }
    }
}

// ---------------- LN3 + relu + bf16 split ----------------
__global__ void ln3_kernel(const float* __restrict__ s3, const float* __restrict__ b3) {
    int cell = blockIdx.x, t = threadIdx.x;
    float v = g_grid[(size_t)cell * 256 + t];
    float s = v, q = v * v;
#pragma unroll
    for (int o = 16; o > 0; o >>= 1) {
        s += __shfl_down_sync(~0u, s, o); q += __shfl_down_sync(~0u, q, o);
    }
    __shared__ float ws[8], wq[8]; __shared__ float sm_, sr_;
    if ((t & 31) == 0) { ws[t >> 5] = s; wq[t >> 5] = q; }
    __syncthreads();
    if (t == 0) {
        s = 0; q = 0;
#pragma unroll
        for (int i = 0; i < 8; i++) { s += ws[i]; q += wq[i]; }
        float m = s / 256.f;
        sm_ = m; sr_ = rsqrtf(q / 256.f - m * m + EPSF);
    }
    __syncthreads();
    float g = fmaxf((v - sm_) * sr_ * s3[t] + b3[t], 0.f);
    bsplit(g, g_gh[(size_t)cell * 256 + t], g_gl[(size_t)cell * 256 + t]);
}

// ---------------- conv via mma.sync (implicit GEMM), same 4-warp tile ----------------
__global__ void __launch_bounds__(128, 2)
conv_mma(const float* __restrict__ cbias, float* __restrict__ outp) {
    extern __shared__ char smv[];
    uint32_t sb = smem_u32(smv);
    int tid = threadIdx.x, wid = tid >> 5, lane = tid & 31;
    int coBase = blockIdx.x * 128;
    int y = blockIdx.y;
    int arow = tid >> 1, half = tid & 1;   // arow = x cell, half = ci half
    int bn = tid;

    float acc[2][8][4];
#pragma unroll
    for (int i = 0; i < 2; i++)
#pragma unroll
        for (int j = 0; j < 8; j++)
#pragma unroll
            for (int e = 0; e < 4; e++) acc[i][j][e] = 0.f;

    int wm = (wid >> 1) * 32, wn = (wid & 1) * 64;
    int lg = lane >> 3, lr8 = lane & 7;

    auto issue = [&](int c, uint32_t stB) {
        int tap = c >> 2, kc = (c & 3) * 64;
        int ky = tap / 3, kx = tap - ky * 3;
        int sy = y + ky - 1, sx = arow + kx - 1;
        bool ok = ((unsigned)sy < 64u) && ((unsigned)sx < 64u);
        size_t aoff = ((size_t)(ok ? (sy * 64 + sx) : 0)) * 256 + kc + half * 32;
        const char* sh = (const char*)(g_gh + aoff);
        const char* sl = (const char*)(g_gl + aoff);
        uint32_t dA = stB + arow * PBY + half * 64;
        int sz = ok ? 16 : 0;
#pragma unroll
        for (int v = 0; v < 4; v++) {
            cpa16z(dA + T_AH + v * 16, sh + v * 16, sz);
            cpa16z(dA + T_AL + v * 16, sl + v * 16, sz);
        }
        size_t boff = (size_t)tap * 65536 + (size_t)(coBase + bn) * 256 + kc;
        const char* bh_ = (const char*)(g_wch + boff);
        const char* bl_ = (const char*)(g_wcl + boff);
        uint32_t dB = stB + bn * PBY;
#pragma unroll
        for (int j2 = 0; j2 < 8; j2++) {
            cpa16(dB + T_BH + j2 * 16, bh_ + j2 * 16);
            cpa16(dB + T_BL + j2 * 16, bl_ + j2 * 16);
        }
    };

    issue(0, sb);
    cpa_commit(); cpa_wait0(); __syncthreads();

    for (int c = 0; c < C_NCH; c++) {
        int cur = c & 1;
        uint32_t curB = sb + cur * T_STG;
        if (c + 1 < C_NCH) issue(c + 1, sb + (cur ^ 1) * T_STG);
#pragma unroll
        for (int ks = 0; ks < 4; ks++) {
            int k0 = ks * 16;
            MMA_K16W(curB, T_AH, T_AL, T_BH, T_BL)
        }
        cpa_commit(); cpa_wait0(); __syncthreads();
    }

    int elr = lane >> 2, elc = (lane & 3) * 2;
#pragma unroll
    for (int i = 0; i < 2; i++) {
        int x0 = wm + i * 16 + elr, x1 = x0 + 8;
#pragma unroll
        for (int jt = 0; jt < 8; jt++) {
            int col = coBase + wn + jt * 8 + elc;
            float b0 = __ldg(cbias + col), b1 = __ldg(cbias + col + 1);
            *(float2*)(outp + ((size_t)(y * 64 + x0)) * 256 + col) =
                make_float2(acc[i][jt][0] + b0, acc[i][jt][1] + b1);
            *(float2*)(outp + ((size_t)(y * 64 + x1)) * 256 + col) =
                make_float2(acc[i][jt][2] + b0, acc[i][jt][3] + b1);
        }
    }
}

// ---------------- launch ----------------
extern "C" void kernel_launch(void* const* d_in, const int* in_sizes, int n_in,
                              void* d_out, int out_size) {
    const float* z     = (const float*)d_in[0];
    const int*   ux    = (const int*)d_in[1];
    const int*   uy    = (const int*)d_in[2];
    const int*   ne    = (const int*)d_in[3];
    const float* ln1_s = (const float*)d_in[4];
    const float* ln1_b = (const float*)d_in[5];
    const float* W1    = (const float*)d_in[6];
    const float* b1    = (const float*)d_in[7];
    const float* ln2_s = (const float*)d_in[8];
    const float* ln2_b = (const float*)d_in[9];
    const float* W2    = (const float*)d_in[10];
    const float* b2    = (const float*)d_in[11];
    const float* ln3_s = (const float*)d_in[12];
    const float* ln3_b = (const float*)d_in[13];
    const float* cw    = (const float*)d_in[14];
    const float* cb    = (const float*)d_in[15];
    float* out = (float*)d_out;
    (void)in_sizes; (void)n_in; (void)out_size;

    cudaFuncSetAttribute(gemm_mma<0>, cudaFuncAttributeMaxDynamicSharedMemorySize, T_SMEM);
    cudaFuncSetAttribute(gemm_mma<1>, cudaFuncAttributeMaxDynamicSharedMemorySize, T_SMEM);
    cudaFuncSetAttribute(conv_mma,    cudaFuncAttributeMaxDynamicSharedMemorySize, T_SMEM);

    setup_kernel<<<4961, 256>>>(W1, W2, cw);
    compact_stats_kernel<<<U_, 128>>>(z, ne);
    gemm_mma<0><<<dim3(4, 512), 128, T_SMEM>>>(z, ln1_s, ln1_b, b1, nullptr, nullptr);
    gemm_mma<1><<<dim3(2, 512), 128, T_SMEM>>>(nullptr, ln2_s, ln2_b, b2, ux, uy);
    ln3_kernel<<<4096, 256>>>(ln3_s, ln3_b);
    conv_mma<<<dim3(2, 64), 128, T_SMEM>>>(cb, out);
}

// round 11
// speedup vs baseline: 1.2640x; 1.2640x over previous
#include <cuda_runtime.h>
#include <cuda_bf16.h>
#include <cstdint>

#define U_   32768
#define EPSF 1e-6f

// ---------------- scratch globals ----------------
__device__ int   g_count;
__device__ int   g_idx[U_];
__device__ float g_mean1[U_], g_rstd1[U_];          // compacted
__device__ float g_sum2[U_], g_sumsq2[U_];          // compacted
__device__ float g_h1[(size_t)U_ * 512];            // compacted rows
__device__ float g_grid[64 * 64 * 256];
__device__ __nv_bfloat16 g_gh[64 * 64 * 256], g_gl[64 * 64 * 256];
__device__ __nv_bfloat16 g_w1h[512 * 512], g_w1l[512 * 512];       // [n][k]
__device__ __nv_bfloat16 g_w2h[256 * 512], g_w2l[256 * 512];       // [n][k]
__device__ __nv_bfloat16 g_wch[9 * 256 * 256], g_wcl[9 * 256 * 256]; // [tap][co][ci]

// ---------------- helpers ----------------
__device__ __forceinline__ uint32_t smem_u32(const void* p) {
    uint32_t a;
    asm("{ .reg .u64 t; cvta.to.shared.u64 t, %1; cvt.u32.u64 %0, t; }" : "=r"(a) : "l"(p));
    return a;
}
__device__ __forceinline__ void cpa16(uint32_t d, const void* s) {
    asm volatile("cp.async.cg.shared.global [%0], [%1], 16;" :: "r"(d), "l"(s));
}
__device__ __forceinline__ void cpa16z(uint32_t d, const void* s, int sz) {
    asm volatile("cp.async.ca.shared.global [%0], [%1], 16, %2;" :: "r"(d), "l"(s), "r"(sz));
}
__device__ __forceinline__ void cpa_commit() { asm volatile("cp.async.commit_group;" ::: "memory"); }
__device__ __forceinline__ void cpa_wait0()  { asm volatile("cp.async.wait_group 0;"  ::: "memory"); }
__device__ __forceinline__ void ldx4(uint32_t* r, uint32_t a) {
    asm volatile("ldmatrix.sync.aligned.m8n8.x4.shared.b16 {%0,%1,%2,%3}, [%4];"
                 : "=r"(r[0]), "=r"(r[1]), "=r"(r[2]), "=r"(r[3]) : "r"(a));
}
__device__ __forceinline__ void mma_bf16(float* c, const uint32_t* a, const uint32_t* b) {
    asm volatile(
        "mma.sync.aligned.m16n8k16.row.col.f32.bf16.bf16.f32 "
        "{%0,%1,%2,%3}, {%4,%5,%6,%7}, {%8,%9}, {%0,%1,%2,%3};"
        : "+f"(c[0]), "+f"(c[1]), "+f"(c[2]), "+f"(c[3])
        : "r"(a[0]), "r"(a[1]), "r"(a[2]), "r"(a[3]), "r"(b[0]), "r"(b[1]));
}
__device__ __forceinline__ void bsplit(float v, __nv_bfloat16& h, __nv_bfloat16& l) {
    h = __float2bfloat16(v);
    l = __float2bfloat16(v - __bfloat162float(h));
}

// ---------------- fused setup ----------------
__global__ void setup_kernel(const float* __restrict__ W1, const float* __restrict__ W2,
                             const float* __restrict__ cw) {
    int b = blockIdx.x, t = threadIdx.x;
    if (b < 1024) {
        ((float4*)g_grid)[b * 256 + t] = make_float4(0, 0, 0, 0);
    } else if (b < 1088) {
        int i = (b - 1024) * 256 + t;
        if (i < 8192) ((float4*)g_sum2)[i] = make_float4(0, 0, 0, 0);
        else ((float4*)g_sumsq2)[i - 8192] = make_float4(0, 0, 0, 0);
    } else if (b < 1120) {
        ((int4*)g_idx)[(b - 1088) * 256 + t] = make_int4(0, 0, 0, 0);
    } else if (b < 1121) {
        if (t == 0) g_count = 0;
    } else if (b < 2145) {
        int i = (b - 1121) * 256 + t;
        int n = i >> 9, k = i & 511;
        bsplit(W1[(size_t)k * 512 + n], g_w1h[(size_t)n * 512 + k], g_w1l[(size_t)n * 512 + k]);
    } else if (b < 2657) {
        int i = (b - 2145) * 256 + t;
        int n = i >> 9, k = i & 511;
        bsplit(W2[(size_t)k * 256 + n], g_w2h[(size_t)n * 512 + k], g_w2l[(size_t)n * 512 + k]);
    } else {
        int i = (b - 2657) * 256 + t;
        int tap = i >> 16, r = i & 65535, co = r >> 8, ci = r & 255;
        bsplit(cw[((size_t)tap * 256 + ci) * 256 + co],
               g_wch[(size_t)tap * 65536 + co * 256 + ci],
               g_wcl[(size_t)tap * 65536 + co * 256 + ci]);
    }
}

// ---------------- compaction + LN1 stats ----------------
__global__ void compact_stats_kernel(const float* __restrict__ z, const int* __restrict__ ne) {
    int row = blockIdx.x;
    if (ne[row] == 0) return;
    __shared__ int spos;
    if (threadIdx.x == 0) spos = atomicAdd(&g_count, 1);
    const float4* xr = (const float4*)(z + (size_t)row * 512);
    float s, q;
    {
        float4 v = xr[threadIdx.x];
        s = v.x + v.y + v.z + v.w;
        q = v.x * v.x + v.y * v.y + v.z * v.z + v.w * v.w;
    }
#pragma unroll
    for (int o = 16; o > 0; o >>= 1) {
        s += __shfl_down_sync(~0u, s, o); q += __shfl_down_sync(~0u, q, o);
    }
    __shared__ float ws[4], wq[4];
    if ((threadIdx.x & 31) == 0) { ws[threadIdx.x >> 5] = s; wq[threadIdx.x >> 5] = q; }
    __syncthreads();
    if (threadIdx.x == 0) {
        int pos = spos;
        s = ws[0] + ws[1] + ws[2] + ws[3]; q = wq[0] + wq[1] + wq[2] + wq[3];
        float m = s / 512.f, v = q / 512.f - m * m;
        g_idx[pos] = row;
        g_mean1[pos] = m; g_rstd1[pos] = rsqrtf(v + EPSF);
    }
}

// ---------------- tiles: M=64, N=128, BK=64; 256 threads, 8 warps (2Mx4N, warp 32x32) ----------------
#define PBY 144
#define T_SA (64 * PBY)
#define T_AH 0
#define T_AL T_SA
#define T_BH (2 * T_SA)
#define T_SB (128 * PBY)
#define T_BL (2 * T_SA + T_SB)
#define T_STG (2 * T_SA + 2 * T_SB)
#define T_SMEM (2 * T_STG)
#define G_NCH 8
#define C_NCH 36

// LN params live in the 16B row tails of the A buffers (bytes 128..144 of each
// 144B row — never touched by cp.async / st.shared / ldmatrix which address
// bytes [0,128) only).  lnS -> stage0 {Ah rows 0..63, Al rows 0..63},
// lnB -> stage1 {Ah, Al}.  Group g = 4 consecutive floats (g in 0..127).
__device__ __forceinline__ uint32_t ln_addr(uint32_t stage_base, int g) {
    return stage_base + ((g < 64) ? (T_AH + g * PBY) : (T_AL + (g - 64) * PBY)) + 128;
}

// LN + relu + split of 16 contiguous values; LN params from smem tails.
__device__ __forceinline__ void lnsplit_store(const float* va, float mA, float rsA,
        uint32_t sb, int kb, uint32_t dAH, uint32_t dAL) {
    float sA[16], bA[16];
    int g0 = kb >> 2;
#pragma unroll
    for (int g = 0; g < 4; g++) {
        uint32_t aS = ln_addr(sb, g0 + g);
        uint32_t aB = ln_addr(sb + T_STG, g0 + g);
        asm volatile("ld.shared.v4.f32 {%0,%1,%2,%3}, [%4];"
                     : "=f"(sA[4*g]), "=f"(sA[4*g+1]), "=f"(sA[4*g+2]), "=f"(sA[4*g+3]) : "r"(aS));
        asm volatile("ld.shared.v4.f32 {%0,%1,%2,%3}, [%4];"
                     : "=f"(bA[4*g]), "=f"(bA[4*g+1]), "=f"(bA[4*g+2]), "=f"(bA[4*g+3]) : "r"(aB));
    }
    uint32_t hi[8], lo[8];
#pragma unroll
    for (int e = 0; e < 8; e++) {
        float a0 = fmaxf((va[2*e]   - mA) * rsA * sA[2*e]   + bA[2*e],   0.f);
        float a1 = fmaxf((va[2*e+1] - mA) * rsA * sA[2*e+1] + bA[2*e+1], 0.f);
        __nv_bfloat162 H, L;
        bsplit(a0, H.x, L.x); bsplit(a1, H.y, L.y);
        hi[e] = *(uint32_t*)&H; lo[e] = *(uint32_t*)&L;
    }
    asm volatile("st.shared.v4.b32 [%0], {%1,%2,%3,%4};" :: "r"(dAH),      "r"(hi[0]), "r"(hi[1]), "r"(hi[2]), "r"(hi[3]));
    asm volatile("st.shared.v4.b32 [%0], {%1,%2,%3,%4};" :: "r"(dAH + 16), "r"(hi[4]), "r"(hi[5]), "r"(hi[6]), "r"(hi[7]));
    asm volatile("st.shared.v4.b32 [%0], {%1,%2,%3,%4};" :: "r"(dAL),      "r"(lo[0]), "r"(lo[1]), "r"(lo[2]), "r"(lo[3]));
    asm volatile("st.shared.v4.b32 [%0], {%1,%2,%3,%4};" :: "r"(dAL + 16), "r"(lo[4]), "r"(lo[5]), "r"(lo[6]), "r"(lo[7]));
}

// 3-pass MMA over one K16 step: 8 independent MMAs per pass (RAW distance 8)
#define MMA_K16(curB, AHOFF, ALOFF, BHOFF, BLOFF)                                              \
    {                                                                                          \
        uint32_t ah[2][4], al[2][4], bh[2][4], bl[2][4];                                       \
        _Pragma("unroll")                                                                      \
        for (int i = 0; i < 2; i++) {                                                          \
            uint32_t ra = (uint32_t)(wm + i * 16 + lr8 + (lg & 1) * 8) * PBY                   \
                        + (k0 + (lg >> 1) * 8) * 2;                                            \
            ldx4(ah[i], (curB) + (AHOFF) + ra);                                                \
            ldx4(al[i], (curB) + (ALOFF) + ra);                                                \
        }                                                                                      \
        _Pragma("unroll")                                                                      \
        for (int j = 0; j < 2; j++) {                                                          \
            uint32_t rb = (uint32_t)(wn + j * 16 + lr8 + (lg >> 1) * 8) * PBY                  \
                        + (k0 + (lg & 1) * 8) * 2;                                             \
            ldx4(bh[j], (curB) + (BHOFF) + rb);                                                \
            ldx4(bl[j], (curB) + (BLOFF) + rb);                                                \
        }                                                                                      \
        _Pragma("unroll")                                                                      \
        for (int i = 0; i < 2; i++)                                                            \
            _Pragma("unroll")                                                                  \
            for (int j = 0; j < 2; j++) {                                                      \
                mma_bf16(acc[i][2*j],     ah[i], bh[j]);                                       \
                mma_bf16(acc[i][2*j + 1], ah[i], bh[j] + 2);                                   \
            }                                                                                  \
        _Pragma("unroll")                                                                      \
        for (int i = 0; i < 2; i++)                                                            \
            _Pragma("unroll")                                                                  \
            for (int j = 0; j < 2; j++) {                                                      \
                mma_bf16(acc[i][2*j],     al[i], bh[j]);                                       \
                mma_bf16(acc[i][2*j + 1], al[i], bh[j] + 2);                                   \
            }                                                                                  \
        _Pragma("unroll")                                                                      \
        for (int i = 0; i < 2; i++)                                                            \
            _Pragma("unroll")                                                                  \
            for (int j = 0; j < 2; j++) {                                                      \
                mma_bf16(acc[i][2*j],     ah[i], bl[j]);                                       \
                mma_bf16(acc[i][2*j + 1], ah[i], bl[j] + 2);                                   \
            }                                                                                  \
    }

template <int MODE>
__global__ void __launch_bounds__(256, 2)
gemm_mma(const float* __restrict__ zin,
         const float* __restrict__ lnS, const float* __restrict__ lnB,
         const float* __restrict__ bias,
         const int* __restrict__ ux, const int* __restrict__ uy) {
    int cnt = g_count;
    int cntPad = (cnt + 63) & ~63;
    int rowBase = blockIdx.y * 64;
    if (rowBase >= cntPad) return;

    extern __shared__ char smv[];
    uint32_t sb = smem_u32(smv);
    int tid = threadIdx.x, wid = tid >> 5, lane = tid & 31;
    int nBase = blockIdx.x * 128;
    const __nv_bfloat16* WhP = (MODE == 0) ? g_w1h : g_w2h;
    const __nv_bfloat16* WlP = (MODE == 0) ? g_w1l : g_w2l;

    // Stage LN params into A-buffer row tails (512 lnS + 512 lnB floats).
    {
        int t2 = tid & 127;
        const float* srcp = (tid < 128) ? lnS : lnB;
        float4 v = *(const float4*)(srcp + t2 * 4);
        uint32_t a = ln_addr(sb + ((tid < 128) ? 0 : T_STG), t2);
        asm volatile("st.shared.v4.f32 [%0], {%1,%2,%3,%4};"
                     :: "r"(a), "f"(v.x), "f"(v.y), "f"(v.z), "f"(v.w));
    }

    // A producer: thread -> (compacted row, 16-float slab)
    int arow = tid >> 2, q = tid & 3;
    int gr = rowBase + arow;
    const float* Arow;
    float mA, rsA;
    if (MODE == 0) {
        mA = g_mean1[gr]; rsA = g_rstd1[gr];
        Arow = zin + (size_t)g_idx[gr] * 512;
    } else {
        float s = g_sum2[gr] * (1.f / 512.f), qq = g_sumsq2[gr] * (1.f / 512.f);
        mA = s; rsA = rsqrtf(qq - s * s + EPSF);
        Arow = g_h1 + (size_t)gr * 512;
    }
    uint32_t dA = arow * PBY + q * 32;
    // B producer: thread -> (n row, 32-elem half)
    int bn = tid >> 1, bhf = tid & 1;
    const char* srcBH = (const char*)(WhP + (size_t)(nBase + bn) * 512) + bhf * 64;
    const char* srcBL = (const char*)(WlP + (size_t)(nBase + bn) * 512) + bhf * 64;
    uint32_t dB = bn * PBY + bhf * 64;

    float acc[2][4][4];
#pragma unroll
    for (int i = 0; i < 2; i++)
#pragma unroll
        for (int j = 0; j < 4; j++)
#pragma unroll
            for (int e = 0; e < 4; e++) acc[i][j][e] = 0.f;

    int wm = (wid >> 2) * 32, wn = (wid & 3) * 32;
    int lg = lane >> 3, lr8 = lane & 7;
    float va[16];

    __syncthreads();   // LN tails visible to all producers

    // prologue: chunk 0 -> stage 0
    {
        const float4* s4 = (const float4*)(Arow + q * 16);
#pragma unroll
        for (int i2 = 0; i2 < 4; i2++) ((float4*)va)[i2] = s4[i2];
#pragma unroll
        for (int j2 = 0; j2 < 4; j2++) {
            cpa16(sb + T_BH + dB + j2 * 16, srcBH + j2 * 16);
            cpa16(sb + T_BL + dB + j2 * 16, srcBL + j2 * 16);
        }
        lnsplit_store(va, mA, rsA, sb, q * 16, sb + T_AH + dA, sb + T_AL + dA);
        cpa_commit(); cpa_wait0(); __syncthreads();
    }

    for (int c = 0; c < G_NCH; c++) {
        int cur = c & 1;
        uint32_t curB = sb + cur * T_STG, nxtB = sb + (cur ^ 1) * T_STG;
        if (c + 1 < G_NCH) {
#pragma unroll
            for (int j2 = 0; j2 < 4; j2++) {
                cpa16(nxtB + T_BH + dB + j2 * 16, srcBH + (c + 1) * 128 + j2 * 16);
                cpa16(nxtB + T_BL + dB + j2 * 16, srcBL + (c + 1) * 128 + j2 * 16);
            }
            const float4* s4 = (const float4*)(Arow + (c + 1) * 64 + q * 16);
#pragma unroll
            for (int i2 = 0; i2 < 4; i2++) ((float4*)va)[i2] = s4[i2];
        }
#pragma unroll
        for (int ks = 0; ks < 4; ks++) {
            int k0 = ks * 16;
            MMA_K16(curB, T_AH, T_AL, T_BH, T_BL)
        }
        if (c + 1 < G_NCH)
            lnsplit_store(va, mA, rsA, sb, (c + 1) * 64 + q * 16,
                          nxtB + T_AH + dA, nxtB + T_AL + dA);
        cpa_commit(); cpa_wait0(); __syncthreads();
    }

    // ---- epilogue ----
    int elr = lane >> 2, elc = (lane & 3) * 2;
#pragma unroll
    for (int i = 0; i < 2; i++) {
        int r0 = rowBase + wm + i * 16 + elr;
        int r1 = r0 + 8;
        if (MODE == 0) {
            float s0 = 0, q0 = 0, s1 = 0, q1 = 0;
#pragma unroll
            for (int jt = 0; jt < 4; jt++) {
                int col = nBase + wn + jt * 8 + elc;
                float b0 = __ldg(bias + col), b1 = __ldg(bias + col + 1);
                float d0 = acc[i][jt][0] + b0, d1 = acc[i][jt][1] + b1;
                float d2 = acc[i][jt][2] + b0, d3 = acc[i][jt][3] + b1;
                *(float2*)(g_h1 + (size_t)r0 * 512 + col) = make_float2(d0, d1);
                *(float2*)(g_h1 + (size_t)r1 * 512 + col) = make_float2(d2, d3);
                s0 += d0 + d1; q0 += d0 * d0 + d1 * d1;
                s1 += d2 + d3; q1 += d2 * d2 + d3 * d3;
            }
#pragma unroll
            for (int o = 1; o < 4; o <<= 1) {
                s0 += __shfl_xor_sync(~0u, s0, o); q0 += __shfl_xor_sync(~0u, q0, o);
                s1 += __shfl_xor_sync(~0u, s1, o); q1 += __shfl_xor_sync(~0u, q1, o);
            }
            if ((lane & 3) == 0) {
                atomicAdd(&g_sum2[r0], s0); atomicAdd(&g_sumsq2[r0], q0);
                atomicAdd(&g_sum2[r1], s1); atomicAdd(&g_sumsq2[r1], q1);
            }
        } else {
            int c0 = -1, c1 = -1;
            if (r0 < cnt) { int o0 = g_idx[r0]; c0 = (uy[o0] * 64 + ux[o0]) * 256; }
            if (r1 < cnt) { int o1 = g_idx[r1]; c1 = (uy[o1] * 64 + ux[o1]) * 256; }
#pragma unroll
            for (int jt = 0; jt < 4; jt++) {
                int col = nBase + wn + jt * 8 + elc;
                float b0 = __ldg(bias + col), b1 = __ldg(bias + col + 1);
                if (c0 >= 0) {
                    atomicAdd(&g_grid[c0 + col],     acc[i][jt][0] + b0);
                    atomicAdd(&g_grid[c0 + col + 1], acc[i][jt][1] + b1);
                }
                if (c1 >= 0) {
                    atomicAdd(&g_grid[c1 + col],     acc[i][jt][2] + b0);
                    atomicAdd(&g_grid[c1 + col + 1], acc[i][jt][3] + b1);
                }
            }
        }
    }
}

// ---------------- LN3 + relu + bf16 split ----------------
__global__ void ln3_kernel(const float* __restrict__ s3, const float* __restrict__ b3) {
    int cell = blockIdx.x, t = threadIdx.x;
    float v = g_grid[(size_t)cell * 256 + t];
    float s = v, q = v * v;
#pragma unroll
    for (int o = 16; o > 0; o >>= 1) {
        s += __shfl_down_sync(~0u, s, o); q += __shfl_down_sync(~0u, q, o);
    }
    __shared__ float ws[8], wq[8]; __shared__ float sm_, sr_;
    if ((t & 31) == 0) { ws[t >> 5] = s; wq[t >> 5] = q; }
    __syncthreads();
    if (t == 0) {
        s = 0; q = 0;
#pragma unroll
        for (int i = 0; i < 8; i++) { s += ws[i]; q += wq[i]; }
        float m = s / 256.f;
        sm_ = m; sr_ = rsqrtf(q / 256.f - m * m + EPSF);
    }
    __syncthreads();
    float g = fmaxf((v - sm_) * sr_ * s3[t] + b3[t], 0.f);
    bsplit(g, g_gh[(size_t)cell * 256 + t], g_gl[(size_t)cell * 256 + t]);
}

// ---------------- conv via mma.sync (implicit GEMM), R9 tile shape ----------------
__global__ void __launch_bounds__(256, 2)
conv_mma(const float* __restrict__ cbias, float* __restrict__ outp) {
    extern __shared__ char smv[];
    uint32_t sb = smem_u32(smv);
    int tid = threadIdx.x, wid = tid >> 5, lane = tid & 31;
    int coBase = blockIdx.x * 128;
    int y = blockIdx.y;
    int arow = tid >> 2, q = tid & 3;   // arow = x cell
    int bn = tid >> 1, bhf = tid & 1;

    float acc[2][4][4];
#pragma unroll
    for (int i = 0; i < 2; i++)
#pragma unroll
        for (int j = 0; j < 4; j++)
#pragma unroll
            for (int e = 0; e < 4; e++) acc[i][j][e] = 0.f;

    int wm = (wid >> 2) * 32, wn = (wid & 3) * 32;
    int lg = lane >> 3, lr8 = lane & 7;

    auto issue = [&](int c, uint32_t stB) {
        int tap = c >> 2, kc = (c & 3) * 64;
        int ky = tap / 3, kx = tap - ky * 3;
        int sy = y + ky - 1, sx = arow + kx - 1;
        bool ok = ((unsigned)sy < 64u) && ((unsigned)sx < 64u);
        size_t aoff = ((size_t)(ok ? (sy * 64 + sx) : 0)) * 256 + kc + q * 16;
        const char* sh = (const char*)(g_gh + aoff);
        const char* sl = (const char*)(g_gl + aoff);
        uint32_t dA = stB + arow * PBY + q * 32;
        int sz = ok ? 16 : 0;
        cpa16z(dA + T_AH,      sh,      sz);
        cpa16z(dA + T_AH + 16, sh + 16, sz);
        cpa16z(dA + T_AL,      sl,      sz);
        cpa16z(dA + T_AL + 16, sl + 16, sz);
        size_t boff = (size_t)tap * 65536 + (size_t)(coBase + bn) * 256 + kc + bhf * 32;
        const char* bh_ = (const char*)(g_wch + boff);
        const char* bl_ = (const char*)(g_wcl + boff);
        uint32_t dB = stB + bn * PBY + bhf * 64;
#pragma unroll
        for (int j2 = 0; j2 < 4; j2++) {
            cpa16(dB + T_BH + j2 * 16, bh_ + j2 * 16);
            cpa16(dB + T_BL + j2 * 16, bl_ + j2 * 16);
        }
    };

    issue(0, sb);
    cpa_commit(); cpa_wait0(); __syncthreads();

    for (int c = 0; c < C_NCH; c++) {
        int cur = c & 1;
        uint32_t curB = sb + cur * T_STG;
        if (c + 1 < C_NCH) issue(c + 1, sb + (cur ^ 1) * T_STG);
#pragma unroll
        for (int ks = 0; ks < 4; ks++) {
            int k0 = ks * 16;
            MMA_K16(curB, T_AH, T_AL, T_BH, T_BL)
        }
        cpa_commit(); cpa_wait0(); __syncthreads();
    }

    int elr = lane >> 2, elc = (lane & 3) * 2;
#pragma unroll
    for (int i = 0; i < 2; i++) {
        int x0 = wm + i * 16 + elr, x1 = x0 + 8;
#pragma unroll
        for (int jt = 0; jt < 4; jt++) {
            int col = coBase + wn + jt * 8 + elc;
            float b0 = __ldg(cbias + col), b1 = __ldg(cbias + col + 1);
            *(float2*)(outp + ((size_t)(y * 64 + x0)) * 256 + col) =
                make_float2(acc[i][jt][0] + b0, acc[i][jt][1] + b1);
            *(float2*)(outp + ((size_t)(y * 64 + x1)) * 256 + col) =
                make_float2(acc[i][jt][2] + b0, acc[i][jt][3] + b1);
        }
    }
}

// ---------------- launch ----------------
extern "C" void kernel_launch(void* const* d_in, const int* in_sizes, int n_in,
                              void* d_out, int out_size) {
    const float* z     = (const float*)d_in[0];
    const int*   ux    = (const int*)d_in[1];
    const int*   uy    = (const int*)d_in[2];
    const int*   ne    = (const int*)d_in[3];
    const float* ln1_s = (const float*)d_in[4];
    const float* ln1_b = (const float*)d_in[5];
    const float* W1    = (const float*)d_in[6];
    const float* b1    = (const float*)d_in[7];
    const float* ln2_s = (const float*)d_in[8];
    const float* ln2_b = (const float*)d_in[9];
    const float* W2    = (const float*)d_in[10];
    const float* b2    = (const float*)d_in[11];
    const float* ln3_s = (const float*)d_in[12];
    const float* ln3_b = (const float*)d_in[13];
    const float* cw    = (const float*)d_in[14];
    const float* cb    = (const float*)d_in[15];
    float* out = (float*)d_out;
    (void)in_sizes; (void)n_in; (void)out_size;

    cudaFuncSetAttribute(gemm_mma<0>, cudaFuncAttributeMaxDynamicSharedMemorySize, T_SMEM);
    cudaFuncSetAttribute(gemm_mma<1>, cudaFuncAttributeMaxDynamicSharedMemorySize, T_SMEM);
    cudaFuncSetAttribute(conv_mma,    cudaFuncAttributeMaxDynamicSharedMemorySize, T_SMEM);

    setup_kernel<<<4961, 256>>>(W1, W2, cw);
    compact_stats_kernel<<<U_, 128>>>(z, ne);
    gemm_mma<0><<<dim3(4, 512), 256, T_SMEM>>>(z, ln1_s, ln1_b, b1, nullptr, nullptr);
    gemm_mma<1><<<dim3(2, 512), 256, T_SMEM>>>(nullptr, ln2_s, ln2_b, b2, ux, uy);
    ln3_kernel<<<4096, 256>>>(ln3_s, ln3_b);
    conv_mma<<<dim3(2, 64), 256, T_SMEM>>>(cb, out);
}

// round 13
// speedup vs baseline: 1.8507x; 1.4642x over previous
#include <cuda_runtime.h>
#include <cuda_fp16.h>
#include <cstdint>

#define U_   32768
#define EPSF 1e-6f

// ---------------- scratch globals ----------------
__device__ int   g_count;
__device__ int   g_idx[U_];
__device__ float g_mean1[U_], g_rstd1[U_];          // compacted
__device__ float g_sum2[U_], g_sumsq2[U_];          // compacted
__device__ float g_h1[(size_t)U_ * 512];            // compacted rows
__device__ float g_grid[64 * 64 * 256];
__device__ __half g_gf[64 * 64 * 256];              // post-LN3 acts, fp16
__device__ __half g_w1f[512 * 512];                 // [n][k]
__device__ __half g_w2f[256 * 512];                 // [n][k]
__device__ __half g_wcf[9 * 256 * 256];             // [tap][co][ci]

// ---------------- helpers ----------------
__device__ __forceinline__ uint32_t smem_u32(const void* p) {
    uint32_t a;
    asm("{ .reg .u64 t; cvta.to.shared.u64 t, %1; cvt.u32.u64 %0, t; }" : "=r"(a) : "l"(p));
    return a;
}
__device__ __forceinline__ void cpa16(uint32_t d, const void* s) {
    asm volatile("cp.async.cg.shared.global [%0], [%1], 16;" :: "r"(d), "l"(s));
}
__device__ __forceinline__ void cpa16z(uint32_t d, const void* s, int sz) {
    asm volatile("cp.async.ca.shared.global [%0], [%1], 16, %2;" :: "r"(d), "l"(s), "r"(sz));
}
__device__ __forceinline__ void cpa_commit() { asm volatile("cp.async.commit_group;" ::: "memory"); }
__device__ __forceinline__ void cpa_wait0()  { asm volatile("cp.async.wait_group 0;"  ::: "memory"); }
__device__ __forceinline__ void ldx4(uint32_t* r, uint32_t a) {
    asm volatile("ldmatrix.sync.aligned.m8n8.x4.shared.b16 {%0,%1,%2,%3}, [%4];"
                 : "=r"(r[0]), "=r"(r[1]), "=r"(r[2]), "=r"(r[3]) : "r"(a));
}
__device__ __forceinline__ void mma_f16(float* c, const uint32_t* a, const uint32_t* b) {
    asm volatile(
        "mma.sync.aligned.m16n8k16.row.col.f32.f16.f16.f32 "
        "{%0,%1,%2,%3}, {%4,%5,%6,%7}, {%8,%9}, {%0,%1,%2,%3};"
        : "+f"(c[0]), "+f"(c[1]), "+f"(c[2]), "+f"(c[3])
        : "r"(a[0]), "r"(a[1]), "r"(a[2]), "r"(a[3]), "r"(b[0]), "r"(b[1]));
}

// ---------------- fused setup ----------------
__global__ void setup_kernel(const float* __restrict__ W1, const float* __restrict__ W2,
                             const float* __restrict__ cw) {
    int b = blockIdx.x, t = threadIdx.x;
    if (b < 1024) {
        ((float4*)g_grid)[b * 256 + t] = make_float4(0, 0, 0, 0);
    } else if (b < 1088) {
        int i = (b - 1024) * 256 + t;
        if (i < 8192) ((float4*)g_sum2)[i] = make_float4(0, 0, 0, 0);
        else ((float4*)g_sumsq2)[i - 8192] = make_float4(0, 0, 0, 0);
    } else if (b < 1120) {
        ((int4*)g_idx)[(b - 1088) * 256 + t] = make_int4(0, 0, 0, 0);
    } else if (b < 1121) {
        if (t == 0) g_count = 0;
    } else if (b < 2145) {                            // W1 [k][n] -> fp16 [n][k]
        int i = (b - 1121) * 256 + t;
        int n = i >> 9, k = i & 511;
        g_w1f[(size_t)n * 512 + k] = __float2half_rn(W1[(size_t)k * 512 + n]);
    } else if (b < 2657) {                            // W2 [k][n] -> fp16 [n][k]
        int i = (b - 2145) * 256 + t;
        int n = i >> 9, k = i & 511;
        g_w2f[(size_t)n * 512 + k] = __float2half_rn(W2[(size_t)k * 256 + n]);
    } else {                                          // conv w [tap][ci][co] -> fp16 [tap][co][ci]
        int i = (b - 2657) * 256 + t;
        int tap = i >> 16, r = i & 65535, co = r >> 8, ci = r & 255;
        g_wcf[(size_t)tap * 65536 + co * 256 + ci] =
            __float2half_rn(cw[((size_t)tap * 256 + ci) * 256 + co]);
    }
}

// ---------------- compaction + LN1 stats ----------------
__global__ void compact_stats_kernel(const float* __restrict__ z, const int* __restrict__ ne) {
    int row = blockIdx.x;
    if (ne[row] == 0) return;
    __shared__ int spos;
    if (threadIdx.x == 0) spos = atomicAdd(&g_count, 1);
    const float4* xr = (const float4*)(z + (size_t)row * 512);
    float s, q;
    {
        float4 v = xr[threadIdx.x];
        s = v.x + v.y + v.z + v.w;
        q = v.x * v.x + v.y * v.y + v.z * v.z + v.w * v.w;
    }
#pragma unroll
    for (int o = 16; o > 0; o >>= 1) {
        s += __shfl_down_sync(~0u, s, o); q += __shfl_down_sync(~0u, q, o);
    }
    __shared__ float ws[4], wq[4];
    if ((threadIdx.x & 31) == 0) { ws[threadIdx.x >> 5] = s; wq[threadIdx.x >> 5] = q; }
    __syncthreads();
    if (threadIdx.x == 0) {
        int pos = spos;
        s = ws[0] + ws[1] + ws[2] + ws[3]; q = wq[0] + wq[1] + wq[2] + wq[3];
        float m = s / 512.f, v = q / 512.f - m * m;
        g_idx[pos] = row;
        g_mean1[pos] = m; g_rstd1[pos] = rsqrtf(v + EPSF);
    }
}

// ---------------- tiles: M=64, N=128, BK=64 fp16; 256 threads, 8 warps (2Mx4N, warp 32x32) ----------------
#define PBY 144
#define T_A 0
#define T_B (64 * PBY)                  // 9216
#define T_STG (T_B + 128 * PBY)         // 27648
#define T_SMEM (2 * T_STG)              // 55296
#define G_NCH 8
#define C_NCH 36

// LN params live in the 16B row tails (bytes 128..144; cp.async/STS/ldmatrix only
// touch [0,128)).  lnS groups 0..63 -> stage0 A tails, 64..127 -> stage1 A tails.
// lnB groups 0..127 -> stage0 B tails.
__device__ __forceinline__ uint32_t lnS_addr(uint32_t sb, int g) {
    return sb + ((g < 64) ? 0u : (uint32_t)T_STG) + (uint32_t)(g & 63) * PBY + T_A + 128;
}
__device__ __forceinline__ uint32_t lnB_addr(uint32_t sb, int g) {
    return sb + T_B + (uint32_t)g * PBY + 128;
}

// LN + relu + fp16 convert of 16 contiguous values; params from smem tails.
__device__ __forceinline__ void lncvt_store(const float* va, float mA, float rsA,
        uint32_t sb, int kb, uint32_t dst) {
    float sA[16], bA[16];
    int g0 = kb >> 2;
#pragma unroll
    for (int g = 0; g < 4; g++) {
        uint32_t aS = lnS_addr(sb, g0 + g);
        uint32_t aB = lnB_addr(sb, g0 + g);
        asm volatile("ld.shared.v4.f32 {%0,%1,%2,%3}, [%4];"
                     : "=f"(sA[4*g]), "=f"(sA[4*g+1]), "=f"(sA[4*g+2]), "=f"(sA[4*g+3]) : "r"(aS));
        asm volatile("ld.shared.v4.f32 {%0,%1,%2,%3}, [%4];"
                     : "=f"(bA[4*g]), "=f"(bA[4*g+1]), "=f"(bA[4*g+2]), "=f"(bA[4*g+3]) : "r"(aB));
    }
    uint32_t hv[8];
#pragma unroll
    for (int e = 0; e < 8; e++) {
        float a0 = fmaxf((va[2*e]   - mA) * rsA * sA[2*e]   + bA[2*e],   0.f);
        float a1 = fmaxf((va[2*e+1] - mA) * rsA * sA[2*e+1] + bA[2*e+1], 0.f);
        __half2 h = __floats2half2_rn(a0, a1);
        hv[e] = *(uint32_t*)&h;
    }
    asm volatile("st.shared.v4.b32 [%0], {%1,%2,%3,%4};" :: "r"(dst),      "r"(hv[0]), "r"(hv[1]), "r"(hv[2]), "r"(hv[3]));
    asm volatile("st.shared.v4.b32 [%0], {%1,%2,%3,%4};" :: "r"(dst + 16), "r"(hv[4]), "r"(hv[5]), "r"(hv[6]), "r"(hv[7]));
}

// Single-pass fp16 MMA over one K16 step: 8 independent MMAs.
#define MMA_K16(curB)                                                                          \
    {                                                                                          \
        uint32_t ah[2][4], bh[2][4];                                                           \
        _Pragma("unroll")                                                                      \
        for (int i = 0; i < 2; i++) {                                                          \
            uint32_t ra = (uint32_t)(wm + i * 16 + lr8 + (lg & 1) * 8) * PBY                   \
                        + (k0 + (lg >> 1) * 8) * 2;                                            \
            ldx4(ah[i], (curB) + T_A + ra);                                                    \
        }                                                                                      \
        _Pragma("unroll")                                                                      \
        for (int j = 0; j < 2; j++) {                                                          \
            uint32_t rb = (uint32_t)(wn + j * 16 + lr8 + (lg >> 1) * 8) * PBY                  \
                        + (k0 + (lg & 1) * 8) * 2;                                             \
            ldx4(bh[j], (curB) + T_B + rb);                                                    \
        }                                                                                      \
        _Pragma("unroll")                                                                      \
        for (int i = 0; i < 2; i++)                                                            \
            _Pragma("unroll")                                                                  \
            for (int j = 0; j < 2; j++) {                                                      \
                mma_f16(acc[i][2*j],     ah[i], bh[j]);                                        \
                mma_f16(acc[i][2*j + 1], ah[i], bh[j] + 2);                                    \
            }                                                                                  \
    }

template <int MODE>
__global__ void __launch_bounds__(256, 2)
gemm_mma(const float* __restrict__ zin,
         const float* __restrict__ lnS, const float* __restrict__ lnB,
         const float* __restrict__ bias,
         const int* __restrict__ ux, const int* __restrict__ uy) {
    int cnt = g_count;
    int cntPad = (cnt + 63) & ~63;
    int rowBase = blockIdx.y * 64;
    if (rowBase >= cntPad) return;

    extern __shared__ char smv[];
    uint32_t sb = smem_u32(smv);
    int tid = threadIdx.x, wid = tid >> 5, lane = tid & 31;
    int nBase = blockIdx.x * 128;
    const __half* Wf = (MODE == 0) ? g_w1f : g_w2f;

    // Stage LN params into row tails.
    {
        int t2 = tid & 127;
        const float* srcp = (tid < 128) ? lnS : lnB;
        float4 v = *(const float4*)(srcp + t2 * 4);
        uint32_t a = (tid < 128) ? lnS_addr(sb, t2) : lnB_addr(sb, t2);
        asm volatile("st.shared.v4.f32 [%0], {%1,%2,%3,%4};"
                     :: "r"(a), "f"(v.x), "f"(v.y), "f"(v.z), "f"(v.w));
    }

    // A producer: thread -> (row, 16-float slab)
    int arow = tid >> 2, q = tid & 3;
    int gr = rowBase + arow;
    const float* Arow;
    float mA, rsA;
    if (MODE == 0) {
        mA = g_mean1[gr]; rsA = g_rstd1[gr];
        Arow = zin + (size_t)g_idx[gr] * 512;
    } else {
        float s = g_sum2[gr] * (1.f / 512.f), qq = g_sumsq2[gr] * (1.f / 512.f);
        mA = s; rsA = rsqrtf(qq - s * s + EPSF);
        Arow = g_h1 + (size_t)gr * 512;
    }
    uint32_t dA = arow * PBY + q * 32;            // q*16 halfs = 32B
    // B producer: thread -> (n row, 32-half half-row)
    int bn = tid >> 1, bhf = tid & 1;
    const char* srcB = (const char*)(Wf + (size_t)(nBase + bn) * 512) + bhf * 64;
    uint32_t dB = T_B + bn * PBY + bhf * 64;

    float acc[2][4][4];
#pragma unroll
    for (int i = 0; i < 2; i++)
#pragma unroll
        for (int j = 0; j < 4; j++)
#pragma unroll
            for (int e = 0; e < 4; e++) acc[i][j][e] = 0.f;

    int wm = (wid >> 2) * 32, wn = (wid & 3) * 32;
    int lg = lane >> 3, lr8 = lane & 7;
    float va[16];

    __syncthreads();   // LN tails visible

    // prologue: chunk 0 -> stage 0
    {
        const float4* s4 = (const float4*)(Arow + q * 16);
#pragma unroll
        for (int i2 = 0; i2 < 4; i2++) ((float4*)va)[i2] = s4[i2];
#pragma unroll
        for (int j2 = 0; j2 < 4; j2++) cpa16(sb + dB + j2 * 16, srcB + j2 * 16);
        lncvt_store(va, mA, rsA, sb, q * 16, sb + T_A + dA);
        cpa_commit(); cpa_wait0(); __syncthreads();
    }

    for (int c = 0; c < G_NCH; c++) {
        int cur = c & 1;
        uint32_t curB = sb + cur * T_STG, nxtB = sb + (cur ^ 1) * T_STG;
        if (c + 1 < G_NCH) {
#pragma unroll
            for (int j2 = 0; j2 < 4; j2++)
                cpa16(nxtB + dB + j2 * 16, srcB + (c + 1) * 128 + j2 * 16);   // FIX: was a
                                                                              // mangled comma-expr
                                                                              // overwriting row byte 0
            const float4* s4 = (const float4*)(Arow + (c + 1) * 64 + q * 16);
#pragma unroll
            for (int i2 = 0; i2 < 4; i2++) ((float4*)va)[i2] = s4[i2];
        }
#pragma unroll
        for (int ks = 0; ks < 4; ks++) {
            int k0 = ks * 16;
            MMA_K16(curB)
        }
        if (c + 1 < G_NCH)
            lncvt_store(va, mA, rsA, sb, (c + 1) * 64 + q * 16, nxtB + T_A + dA);
        cpa_commit(); cpa_wait0(); __syncthreads();
    }

    // ---- epilogue ----
    int elr = lane >> 2, elc = (lane & 3) * 2;
#pragma unroll
    for (int i = 0; i < 2; i++) {
        int r0 = rowBase + wm + i * 16 + elr;
        int r1 = r0 + 8;
        if (MODE == 0) {
            float s0 = 0, q0 = 0, s1 = 0, q1 = 0;
#pragma unroll
            for (int jt = 0; jt < 4; jt++) {
                int col = nBase + wn + jt * 8 + elc;
                float b0 = __ldg(bias + col), b1 = __ldg(bias + col + 1);
                float d0 = acc[i][jt][0] + b0, d1 = acc[i][jt][1] + b1;
                float d2 = acc[i][jt][2] + b0, d3 = acc[i][jt][3] + b1;
                *(float2*)(g_h1 + (size_t)r0 * 512 + col) = make_float2(d0, d1);
                *(float2*)(g_h1 + (size_t)r1 * 512 + col) = make_float2(d2, d3);
                s0 += d0 + d1; q0 += d0 * d0 + d1 * d1;
                s1 += d2 + d3; q1 += d2 * d2 + d3 * d3;
            }
#pragma unroll
            for (int o = 1; o < 4; o <<= 1) {
                s0 += __shfl_xor_sync(~0u, s0, o); q0 += __shfl_xor_sync(~0u, q0, o);
                s1 += __shfl_xor_sync(~0u, s1, o); q1 += __shfl_xor_sync(~0u, q1, o);
            }
            if ((lane & 3) == 0) {
                atomicAdd(&g_sum2[r0], s0); atomicAdd(&g_sumsq2[r0], q0);
                atomicAdd(&g_sum2[r1], s1); atomicAdd(&g_sumsq2[r1], q1);
            }
        } else {
            int c0 = -1, c1 = -1;
            if (r0 < cnt) { int o0 = g_idx[r0]; c0 = (uy[o0] * 64 + ux[o0]) * 256; }
            if (r1 < cnt) { int o1 = g_idx[r1]; c1 = (uy[o1] * 64 + ux[o1]) * 256; }
#pragma unroll
            for (int jt = 0; jt < 4; jt++) {
                int col = nBase + wn + jt * 8 + elc;
                float b0 = __ldg(bias + col), b1 = __ldg(bias + col + 1);
                if (c0 >= 0) {
                    atomicAdd(&g_grid[c0 + col],     acc[i][jt][0] + b0);
                    atomicAdd(&g_grid[c0 + col + 1], acc[i][jt][1] + b1);
                }
                if (c1 >= 0) {
                    atomicAdd(&g_grid[c1 + col],     acc[i][jt][2] + b0);
                    atomicAdd(&g_grid[c1 + col + 1], acc[i][jt][3] + b1);
                }
            }
        }
    }
}

// ---------------- LN3 + relu + fp16 convert ----------------
__global__ void ln3_kernel(const float* __restrict__ s3, const float* __restrict__ b3) {
    int cell = blockIdx.x, t = threadIdx.x;
    float v = g_grid[(size_t)cell * 256 + t];
    float s = v, q = v * v;
#pragma unroll
    for (int o = 16; o > 0; o >>= 1) {
        s += __shfl_down_sync(~0u, s, o); q += __shfl_down_sync(~0u, q, o);
    }
    __shared__ float ws[8], wq[8]; __shared__ float sm_, sr_;
    if ((t & 31) == 0) { ws[t >> 5] = s; wq[t >> 5] = q; }
    __syncthreads();
    if (t == 0) {
        s = 0; q = 0;
#pragma unroll
        for (int i = 0; i < 8; i++) { s += ws[i]; q += wq[i]; }
        float m = s / 256.f;
        sm_ = m; sr_ = rsqrtf(q / 256.f - m * m + EPSF);
    }
    __syncthreads();
    float g = fmaxf((v - sm_) * sr_ * s3[t] + b3[t], 0.f);
    g_gf[(size_t)cell * 256 + t] = __float2half_rn(g);
}

// ---------------- conv via mma.sync (implicit GEMM), fp16 single-pass ----------------
__global__ void __launch_bounds__(256, 2)
conv_mma(const float* __restrict__ cbias, float* __restrict__ outp) {
    extern __shared__ char smv[];
    uint32_t sb = smem_u32(smv);
    int tid = threadIdx.x, wid = tid >> 5, lane = tid & 31;
    int coBase = blockIdx.x * 128;
    int y = blockIdx.y;
    int arow = tid >> 2, q = tid & 3;   // arow = x cell
    int bn = tid >> 1, bhf = tid & 1;

    float acc[2][4][4];
#pragma unroll
    for (int i = 0; i < 2; i++)
#pragma unroll
        for (int j = 0; j < 4; j++)
#pragma unroll
            for (int e = 0; e < 4; e++) acc[i][j][e] = 0.f;

    int wm = (wid >> 2) * 32, wn = (wid & 3) * 32;
    int lg = lane >> 3, lr8 = lane & 7;

    auto issue = [&](int c, uint32_t stB) {
        int tap = c >> 2, kc = (c & 3) * 64;
        int ky = tap / 3, kx = tap - ky * 3;
        int sy = y + ky - 1, sx = arow + kx - 1;
        bool ok = ((unsigned)sy < 64u) && ((unsigned)sx < 64u);
        size_t aoff = ((size_t)(ok ? (sy * 64 + sx) : 0)) * 256 + kc + q * 16;   // halfs
        const char* sh = (const char*)(g_gf + aoff);
        uint32_t dA = stB + T_A + arow * PBY + q * 32;
        int sz = ok ? 16 : 0;
        cpa16z(dA,      sh,      sz);
        cpa16z(dA + 16, sh + 16, sz);
        size_t boff = (size_t)tap * 65536 + (size_t)(coBase + bn) * 256 + kc + bhf * 32; // halfs
        const char* bsrc = (const char*)(g_wcf + boff);
        uint32_t dB = stB + T_B + bn * PBY + bhf * 64;
#pragma unroll
        for (int j2 = 0; j2 < 4; j2++) cpa16(dB + j2 * 16, bsrc + j2 * 16);
    };

    issue(0, sb);
    cpa_commit(); cpa_wait0(); __syncthreads();

    for (int c = 0; c < C_NCH; c++) {
        int cur = c & 1;
        uint32_t curB = sb + cur * T_STG;
        if (c + 1 < C_NCH) issue(c + 1, sb + (cur ^ 1) * T_STG);
#pragma unroll
        for (int ks = 0; ks < 4; ks++) {
            int k0 = ks * 16;
            MMA_K16(curB)
        }
        cpa_commit(); cpa_wait0(); __syncthreads();
    }

    int elr = lane >> 2, elc = (lane & 3) * 2;
#pragma unroll
    for (int i = 0; i < 2; i++) {
        int x0 = wm + i * 16 + elr, x1 = x0 + 8;
#pragma unroll
        for (int jt = 0; jt < 4; jt++) {
            int col = coBase + wn + jt * 8 + elc;
            float b0 = __ldg(cbias + col), b1 = __ldg(cbias + col + 1);
            *(float2*)(outp + ((size_t)(y * 64 + x0)) * 256 + col) =
                make_float2(acc[i][jt][0] + b0, acc[i][jt][1] + b1);
            *(float2*)(outp + ((size_t)(y * 64 + x1)) * 256 + col) =
                make_float2(acc[i][jt][2] + b0, acc[i][jt][3] + b1);
        }
    }
}

// ---------------- launch ----------------
extern "C" void kernel_launch(void* const* d_in, const int* in_sizes, int n_in,
                              void* d_out, int out_size) {
    const float* z     = (const float*)d_in[0];
    const int*   ux    = (const int*)d_in[1];
    const int*   uy    = (const int*)d_in[2];
    const int*   ne    = (const int*)d_in[3];
    const float* ln1_s = (const float*)d_in[4];
    const float* ln1_b = (const float*)d_in[5];
    const float* W1    = (const float*)d_in[6];
    const float* b1    = (const float*)d_in[7];
    const float* ln2_s = (const float*)d_in[8];
    const float* ln2_b = (const float*)d_in[9];
    const float* W2    = (const float*)d_in[10];
    const float* b2    = (const float*)d_in[11];
    const float* ln3_s = (const float*)d_in[12];
    const float* ln3_b = (const float*)d_in[13];
    const float* cw    = (const float*)d_in[14];
    const float* cb    = (const float*)d_in[15];
    float* out = (float*)d_out;
    (void)in_sizes; (void)n_in; (void)out_size;

    cudaFuncSetAttribute(gemm_mma<0>, cudaFuncAttributeMaxDynamicSharedMemorySize, T_SMEM);
    cudaFuncSetAttribute(gemm_mma<1>, cudaFuncAttributeMaxDynamicSharedMemorySize, T_SMEM);
    cudaFuncSetAttribute(conv_mma,    cudaFuncAttributeMaxDynamicSharedMemorySize, T_SMEM);

    setup_kernel<<<4961, 256>>>(W1, W2, cw);
    compact_stats_kernel<<<U_, 128>>>(z, ne);
    gemm_mma<0><<<dim3(4, 512), 256, T_SMEM>>>(z, ln1_s, ln1_b, b1, nullptr, nullptr);
    gemm_mma<1><<<dim3(2, 512), 256, T_SMEM>>>(nullptr, ln2_s, ln2_b, b2, ux, uy);
    ln3_kernel<<<4096, 256>>>(ln3_s, ln3_b);
    conv_mma<<<dim3(2, 64), 256, T_SMEM>>>(cb, out);
}

// round 15
// speedup vs baseline: 2.0630x; 1.1148x over previous
#include <cuda_runtime.h>
#include <cuda_fp16.h>
#include <cstdint>

#define U_   32768
#define EPSF 1e-6f

// ---------------- scratch globals ----------------
__device__ int   g_count;
__device__ int   g_idx[U_];
__device__ float g_sum2[U_], g_sumsq2[U_];          // compacted
__device__ float g_h1[(size_t)U_ * 512];            // compacted rows, f32
__device__ __half g_af[(size_t)U_ * 512];           // compacted relu(LN1(z)), fp16
__device__ float g_grid[64 * 64 * 256];
__device__ __half g_gf[64 * 64 * 256];              // post-LN3 acts, fp16
__device__ __half g_w1f[512 * 512];                 // [n][k]
__device__ __half g_w2f[256 * 512];                 // [n][k]
__device__ __half g_wcf[9 * 256 * 256];             // [tap][co][ci]

// ---------------- helpers ----------------
__device__ __forceinline__ uint32_t smem_u32(const void* p) {
    uint32_t a;
    asm("{ .reg .u64 t; cvta.to.shared.u64 t, %1; cvt.u32.u64 %0, t; }" : "=r"(a) : "l"(p));
    return a;
}
__device__ __forceinline__ void cpa16(uint32_t d, const void* s) {
    asm volatile("cp.async.cg.shared.global [%0], [%1], 16;" :: "r"(d), "l"(s));
}
__device__ __forceinline__ void cpa16z(uint32_t d, const void* s, int sz) {
    asm volatile("cp.async.ca.shared.global [%0], [%1], 16, %2;" :: "r"(d), "l"(s), "r"(sz));
}
__device__ __forceinline__ void cpa_commit() { asm volatile("cp.async.commit_group;" ::: "memory"); }
__device__ __forceinline__ void cpa_wait0()  { asm volatile("cp.async.wait_group 0;"  ::: "memory"); }
__device__ __forceinline__ void ldx4(uint32_t* r, uint32_t a) {
    asm volatile("ldmatrix.sync.aligned.m8n8.x4.shared.b16 {%0,%1,%2,%3}, [%4];"
                 : "=r"(r[0]), "=r"(r[1]), "=r"(r[2]), "=r"(r[3]) : "r"(a));
}
__device__ __forceinline__ void mma_f16(float* c, const uint32_t* a, const uint32_t* b) {
    asm volatile(
        "mma.sync.aligned.m16n8k16.row.col.f32.f16.f16.f32 "
        "{%0,%1,%2,%3}, {%4,%5,%6,%7}, {%8,%9}, {%0,%1,%2,%3};"
        : "+f"(c[0]), "+f"(c[1]), "+f"(c[2]), "+f"(c[3])
        : "r"(a[0]), "r"(a[1]), "r"(a[2]), "r"(a[3]), "r"(b[0]), "r"(b[1]));
}

// ---------------- fused setup ----------------
__global__ void setup_kernel(const float* __restrict__ W1, const float* __restrict__ W2,
                             const float* __restrict__ cw) {
    int b = blockIdx.x, t = threadIdx.x;
    if (b < 1024) {
        ((float4*)g_grid)[b * 256 + t] = make_float4(0, 0, 0, 0);
    } else if (b < 1088) {
        int i = (b - 1024) * 256 + t;
        if (i < 8192) ((float4*)g_sum2)[i] = make_float4(0, 0, 0, 0);
        else ((float4*)g_sumsq2)[i - 8192] = make_float4(0, 0, 0, 0);
    } else if (b < 1120) {
        ((int4*)g_idx)[(b - 1088) * 256 + t] = make_int4(0, 0, 0, 0);
    } else if (b < 1121) {
        if (t == 0) g_count = 0;
    } else if (b < 2145) {                            // W1 [k][n] -> fp16 [n][k]
        int i = (b - 1121) * 256 + t;
        int n = i >> 9, k = i & 511;
        g_w1f[(size_t)n * 512 + k] = __float2half_rn(W1[(size_t)k * 512 + n]);
    } else if (b < 2657) {                            // W2 [k][n] -> fp16 [n][k]
        int i = (b - 2145) * 256 + t;
        int n = i >> 9, k = i & 511;
        g_w2f[(size_t)n * 512 + k] = __float2half_rn(W2[(size_t)k * 256 + n]);
    } else {                                          // conv w [tap][ci][co] -> fp16 [tap][co][ci]
        int i = (b - 2657) * 256 + t;
        int tap = i >> 16, r = i & 65535, co = r >> 8, ci = r & 255;
        g_wcf[(size_t)tap * 65536 + co * 256 + ci] =
            __float2half_rn(cw[((size_t)tap * 256 + ci) * 256 + co]);
    }
}

// ---------------- compaction + LN1 stats + fp16 A1 conversion ----------------
__global__ void compact_stats_kernel(const float* __restrict__ z, const int* __restrict__ ne,
                                     const float* __restrict__ lnS, const float* __restrict__ lnB) {
    int row = blockIdx.x;
    if (ne[row] == 0) return;
    __shared__ int spos;
    if (threadIdx.x == 0) spos = atomicAdd(&g_count, 1);
    float4 v = ((const float4*)(z + (size_t)row * 512))[threadIdx.x];
    float s = v.x + v.y + v.z + v.w;
    float q = v.x * v.x + v.y * v.y + v.z * v.z + v.w * v.w;
#pragma unroll
    for (int o = 16; o > 0; o >>= 1) {
        s += __shfl_down_sync(~0u, s, o); q += __shfl_down_sync(~0u, q, o);
    }
    __shared__ float ws[4], wq[4];
    __shared__ float sm_, sr_;
    if ((threadIdx.x & 31) == 0) { ws[threadIdx.x >> 5] = s; wq[threadIdx.x >> 5] = q; }
    __syncthreads();
    if (threadIdx.x == 0) {
        s = ws[0] + ws[1] + ws[2] + ws[3]; q = wq[0] + wq[1] + wq[2] + wq[3];
        float m = s / 512.f, var = q / 512.f - m * m;
        sm_ = m; sr_ = rsqrtf(var + EPSF);
        g_idx[spos] = row;
    }
    __syncthreads();
    int pos = spos;
    float m = sm_, rs = sr_;
    int k = threadIdx.x * 4;
    float4 sv = *(const float4*)(lnS + k);
    float4 bv = *(const float4*)(lnB + k);
    float a0 = fmaxf((v.x - m) * rs * sv.x + bv.x, 0.f);
    float a1 = fmaxf((v.y - m) * rs * sv.y + bv.y, 0.f);
    float a2 = fmaxf((v.z - m) * rs * sv.z + bv.z, 0.f);
    float a3 = fmaxf((v.w - m) * rs * sv.w + bv.w, 0.f);
    __half2 h01 = __floats2half2_rn(a0, a1);
    __half2 h23 = __floats2half2_rn(a2, a3);
    uint2 pk = make_uint2(*(uint32_t*)&h01, *(uint32_t*)&h23);
    ((uint2*)(g_af + (size_t)pos * 512))[threadIdx.x] = pk;
}

// ---------------- tiles: M=64, N=128, BK=64 fp16; 256 threads, 8 warps (2Mx4N, warp 32x32) ----------------
#define PBY 144
#define T_A 0
#define T_B (64 * PBY)                  // 9216
#define T_STG (T_B + 128 * PBY)         // 27648
#define T_SMEM (2 * T_STG)              // 55296
#define G_NCH 8
#define C_NCH 36

// MODE 1 only: LN2 params in 16B row tails (bytes 128..144, untouched by tiles).
__device__ __forceinline__ uint32_t lnS_addr(uint32_t sb, int g) {
    return sb + ((g < 64) ? 0u : (uint32_t)T_STG) + (uint32_t)(g & 63) * PBY + T_A + 128;
}
__device__ __forceinline__ uint32_t lnB_addr(uint32_t sb, int g) {
    return sb + T_B + (uint32_t)g * PBY + 128;
}

__device__ __forceinline__ void lncvt_store(const float* va, float mA, float rsA,
        uint32_t sb, int kb, uint32_t dst) {
    float sA[16], bA[16];
    int g0 = kb >> 2;
#pragma unroll
    for (int g = 0; g < 4; g++) {
        uint32_t aS = lnS_addr(sb, g0 + g);
        uint32_t aB = lnB_addr(sb, g0 + g);
        asm volatile("ld.shared.v4.f32 {%0,%1,%2,%3}, [%4];"
                     : "=f"(sA[4*g]), "=f"(sA[4*g+1]), "=f"(sA[4*g+2]), "=f"(sA[4*g+3]) : "r"(aS));
        asm volatile("ld.shared.v4.f32 {%0,%1,%2,%3}, [%4];"
                     : "=f"(bA[4*g]), "=f"(bA[4*g+1]), "=f"(bA[4*g+2]), "=f"(bA[4*g+3]) : "r"(aB));
    }
    uint32_t hv[8];
#pragma unroll
    for (int e = 0; e < 8; e++) {
        float a0 = fmaxf((va[2*e]   - mA) * rsA * sA[2*e]   + bA[2*e],   0.f);
        float a1 = fmaxf((va[2*e+1] - mA) * rsA * sA[2*e+1] + bA[2*e+1], 0.f);
        __half2 h = __floats2half2_rn(a0, a1);
        hv[e] = *(uint32_t*)&h;
    }
    asm volatile("st.shared.v4.b32 [%0], {%1,%2,%3,%4};" :: "r"(dst),      "r"(hv[0]), "r"(hv[1]), "r"(hv[2]), "r"(hv[3]));
    asm volatile("st.shared.v4.b32 [%0], {%1,%2,%3,%4};" :: "r"(dst + 16), "r"(hv[4]), "r"(hv[5]), "r"(hv[6]), "r"(hv[7]));
}

// Single-pass fp16 MMA over one K16 step: 8 independent MMAs.
#define MMA_K16(curB)                                                                          \
    {                                                                                          \
        uint32_t ah[2][4], bh[2][4];                                                           \
        _Pragma("unroll")                                                                      \
        for (int i = 0; i < 2; i++) {                                                          \
            uint32_t ra = (uint32_t)(wm + i * 16 + lr8 + (lg & 1) * 8) * PBY                   \
                        + (k0 + (lg >> 1) * 8) * 2;                                            \
            ldx4(ah[i], (curB) + T_A + ra);                                                    \
        }                                                                                      \
        _Pragma("unroll")                                                                      \
        for (int j = 0; j < 2; j++) {                                                          \
            uint32_t rb = (uint32_t)(wn + j * 16 + lr8 + (lg >> 1) * 8) * PBY                  \
                        + (k0 + (lg & 1) * 8) * 2;                                             \
            ldx4(bh[j], (curB) + T_B + rb);                                                    \
        }                                                                                      \
        _Pragma("unroll")                                                                      \
        for (int i = 0; i < 2; i++)                                                            \
            _Pragma("unroll")                                                                  \
            for (int j = 0; j < 2; j++) {                                                      \
                mma_f16(acc[i][2*j],     ah[i], bh[j]);                                        \
                mma_f16(acc[i][2*j + 1], ah[i], bh[j] + 2);                                    \
            }                                                                                  \
    }

template <int MODE>
__global__ void __launch_bounds__(256, 2)
gemm_mma(const float* __restrict__ lnS, const float* __restrict__ lnB,
         const float* __restrict__ bias,
         const int* __restrict__ ux, const int* __restrict__ uy) {
    int cnt = g_count;
    int cntPad = (cnt + 63) & ~63;
    int rowBase = blockIdx.y * 64;
    if (rowBase >= cntPad) return;

    extern __shared__ char smv[];
    uint32_t sb = smem_u32(smv);
    int tid = threadIdx.x, wid = tid >> 5, lane = tid & 31;
    int nBase = blockIdx.x * 128;
    const __half* Wf = (MODE == 0) ? g_w1f : g_w2f;

    // A producer setup
    int arow = tid >> 2, q = tid & 3;
    int gr = rowBase + arow;
    uint32_t dA = arow * PBY + q * 32;            // 16 halfs = 32B per thread
    const char* srcA = nullptr;                   // MODE 0: fp16 async path
    const float* Arow = nullptr;                  // MODE 1: f32 + LN path
    float mA = 0.f, rsA = 0.f;
    if (MODE == 0) {
        srcA = (const char*)(g_af + (size_t)gr * 512) + q * 32;
    } else {
        float s = g_sum2[gr] * (1.f / 512.f), qq = g_sumsq2[gr] * (1.f / 512.f);
        mA = s; rsA = rsqrtf(qq - s * s + EPSF);
        Arow = g_h1 + (size_t)gr * 512;
        // Stage LN2 params into row tails.
        int t2 = tid & 127;
        const float* srcp = (tid < 128) ? lnS : lnB;
        float4 v = *(const float4*)(srcp + t2 * 4);
        uint32_t a = (tid < 128) ? lnS_addr(sb, t2) : lnB_addr(sb, t2);
        asm volatile("st.shared.v4.f32 [%0], {%1,%2,%3,%4};"
                     :: "r"(a), "f"(v.x), "f"(v.y), "f"(v.z), "f"(v.w));
    }
    // B producer: thread -> (n row, 32-half half-row)
    int bn = tid >> 1, bhf = tid & 1;
    const char* srcB = (const char*)(Wf + (size_t)(nBase + bn) * 512) + bhf * 64;
    uint32_t dB = T_B + bn * PBY + bhf * 64;

    float acc[2][4][4];
#pragma unroll
    for (int i = 0; i < 2; i++)
#pragma unroll
        for (int j = 0; j < 4; j++)
#pragma unroll
            for (int e = 0; e < 4; e++) acc[i][j][e] = 0.f;

    int wm = (wid >> 2) * 32, wn = (wid & 3) * 32;
    int lg = lane >> 3, lr8 = lane & 7;
    float va[16];

    if (MODE == 1) __syncthreads();   // LN tails visible

    // prologue: chunk 0 -> stage 0
    {
#pragma unroll
        for (int j2 = 0; j2 < 4; j2++) cpa16(sb + dB + j2 * 16, srcB + j2 * 16);
        if (MODE == 0) {
            cpa16(sb + T_A + dA,      srcA);
            cpa16(sb + T_A + dA + 16, srcA + 16);
        } else {
            const float4* s4 = (const float4*)(Arow + q * 16);
#pragma unroll
            for (int i2 = 0; i2 < 4; i2++) ((float4*)va)[i2] = s4[i2];
            lncvt_store(va, mA, rsA, sb, q * 16, sb + T_A + dA);
        }
        cpa_commit(); cpa_wait0(); __syncthreads();
    }

    for (int c = 0; c < G_NCH; c++) {
        int cur = c & 1;
        uint32_t curB = sb + cur * T_STG, nxtB = sb + (cur ^ 1) * T_STG;
        if (c + 1 < G_NCH) {
#pragma unroll
            for (int j2 = 0; j2 < 4; j2++)
                cpa16(nxtB + dB + j2 * 16, srcB + (c + 1) * 128 + j2 * 16);
            if (MODE == 0) {
                cpa16(nxtB + T_A + dA,      srcA + (c + 1) * 128);
                cpa16(nxtB + T_A + dA + 16, srcA + (c + 1) * 128 + 16);
            } else {
                const float4* s4 = (const float4*)(Arow + (c + 1) * 64 + q * 16);
#pragma unroll
                for (int i2 = 0; i2 < 4; i2++) ((float4*)va)[i2] = s4[i2];
            }
        }
#pragma unroll
        for (int ks = 0; ks < 4; ks++) {
            int k0 = ks * 16;
            MMA_K16(curB)
        }
        if (MODE == 1 && c + 1 < G_NCH)
            lncvt_store(va, mA, rsA, sb, (c + 1) * 64 + q * 16, nxtB + T_A + dA);
        cpa_commit(); cpa_wait0(); __syncthreads();
    }

    // ---- epilogue ----
    int elr = lane >> 2, elc = (lane & 3) * 2;
#pragma unroll
    for (int i = 0; i < 2; i++) {
        int r0 = rowBase + wm + i * 16 + elr;
        int r1 = r0 + 8;
        if (MODE == 0) {
            float s0 = 0, q0 = 0, s1 = 0, q1 = 0;
#pragma unroll
            for (int jt = 0; jt < 4; jt++) {
                int col = nBase + wn + jt * 8 + elc;
                float b0 = __ldg(bias + col), b1 = __ldg(bias + col + 1);
                float d0 = acc[i][jt][0] + b0, d1 = acc[i][jt][1] + b1;
                float d2 = acc[i][jt][2] + b0, d3 = acc[i][jt][3] + b1;
                *(float2*)(g_h1 + (size_t)r0 * 512 + col) = make_float2(d0, d1);
                *(float2*)(g_h1 + (size_t)r1 * 512 + col) = make_float2(d2, d3);
                s0 += d0 + d1; q0 += d0 * d0 + d1 * d1;
                s1 += d2 + d3; q1 += d2 * d2 + d3 * d3;
            }
#pragma unroll
            for (int o = 1; o < 4; o <<= 1) {
                s0 += __shfl_xor_sync(~0u, s0, o); q0 += __shfl_xor_sync(~0u, q0, o);
                s1 += __shfl_xor_sync(~0u, s1, o); q1 += __shfl_xor_sync(~0u, q1, o);
            }
            if ((lane & 3) == 0) {
                atomicAdd(&g_sum2[r0], s0); atomicAdd(&g_sumsq2[r0], q0);
                atomicAdd(&g_sum2[r1], s1); atomicAdd(&g_sumsq2[r1], q1);
            }
        } else {
            int c0 = -1, c1 = -1;
            if (r0 < cnt) { int o0 = g_idx[r0]; c0 = (uy[o0] * 64 + ux[o0]) * 256; }
            if (r1 < cnt) { int o1 = g_idx[r1]; c1 = (uy[o1] * 64 + ux[o1]) * 256; }
#pragma unroll
            for (int jt = 0; jt < 4; jt++) {
                int col = nBase + wn + jt * 8 + elc;
                float b0 = __ldg(bias + col), b1 = __ldg(bias + col + 1);
                if (c0 >= 0) {
                    atomicAdd(&g_grid[c0 + col],     acc[i][jt][0] + b0);
                    atomicAdd(&g_grid[c0 + col + 1], acc[i][jt][1] + b1);
                }
                if (c1 >= 0) {
                    atomicAdd(&g_grid[c1 + col],     acc[i][jt][2] + b0);
                    atomicAdd(&g_grid[c1 + col + 1], acc[i][jt][3] + b1);
                }
            }
        }
    }
}

// ---------------- LN3 + relu + fp16 convert ----------------
__global__ void ln3_kernel(const float* __restrict__ s3, const float* __restrict__ b3) {
    int cell = blockIdx.x, t = threadIdx.x;
    float v = g_grid[(size_t)cell * 256 + t];
    float s = v, q = v * v;
#pragma unroll
    for (int o = 16; o > 0; o >>= 1) {
        s += __shfl_down_sync(~0u, s, o); q += __shfl_down_sync(~0u, q, o);
    }
    __shared__ float ws[8], wq[8]; __shared__ float sm_, sr_;
    if ((t & 31) == 0) { ws[t >> 5] = s; wq[t >> 5] = q; }
    __syncthreads();
    if (t == 0) {
        s = 0; q = 0;
#pragma unroll
        for (int i = 0; i < 8; i++) { s += ws[i]; q += wq[i]; }
        float m = s / 256.f;
        sm_ = m; sr_ = rsqrtf(q / 256.f - m * m + EPSF);
    }
    __syncthreads();
    float g = fmaxf((v - sm_) * sr_ * s3[t] + b3[t], 0.f);
    g_gf[(size_t)cell * 256 + t] = __float2half_rn(g);
}

// ---------------- conv via mma.sync (implicit GEMM), fp16 single-pass ----------------
__global__ void __launch_bounds__(256, 2)
conv_mma(const float* __restrict__ cbias, float* __restrict__ outp) {
    extern __shared__ char smv[];
    uint32_t sb = smem_u32(smv);
    int tid = threadIdx.x, wid = tid >> 5, lane = tid & 31;
    int coBase = blockIdx.x * 128;
    int y = blockIdx.y;
    int arow = tid >> 2, q = tid & 3;   // arow = x cell
    int bn = tid >> 1, bhf = tid & 1;

    float acc[2][4][4];
#pragma unroll
    for (int i = 0; i < 2; i++)
#pragma unroll
        for (int j = 0; j < 4; j++)
#pragma unroll
            for (int e = 0; e < 4; e++) acc[i][j][e] = 0.f;

    int wm = (wid >> 2) * 32, wn = (wid & 3) * 32;
    int lg = lane >> 3, lr8 = lane & 7;

    auto issue = [&](int c, uint32_t stB) {
        int tap = c >> 2, kc = (c & 3) * 64;
        int ky = tap / 3, kx = tap - ky * 3;
        int sy = y + ky - 1, sx = arow + kx - 1;
        bool ok = ((unsigned)sy < 64u) && ((unsigned)sx < 64u);
        size_t aoff = ((size_t)(ok ? (sy * 64 + sx) : 0)) * 256 + kc + q * 16;   // halfs
        const char* sh = (const char*)(g_gf + aoff);
        uint32_t dA = stB + T_A + arow * PBY + q * 32;
        int sz = ok ? 16 : 0;
        cpa16z(dA,      sh,      sz);
        cpa16z(dA + 16, sh + 16, sz);
        size_t boff = (size_t)tap * 65536 + (size_t)(coBase + bn) * 256 + kc + bhf * 32; // halfs
        const char* bsrc = (const char*)(g_wcf + boff);
        uint32_t dB = stB + T_B + bn * PBY + bhf * 64;
#pragma unroll
        for (int j2 = 0; j2 < 4; j2++) cpa16(dB + j2 * 16, bsrc + j2 * 16);
    };

    issue(0, sb);
    cpa_commit(); cpa_wait0(); __syncthreads();

    for (int c = 0; c < C_NCH; c++) {
        int cur = c & 1;
        uint32_t curB = sb + cur * T_STG;
        if (c + 1 < C_NCH) issue(c + 1, sb + (cur ^ 1) * T_STG);
#pragma unroll
        for (int ks = 0; ks < 4; ks++) {
            int k0 = ks * 16;
            MMA_K16(curB)
        }
        cpa_commit(); cpa_wait0(); __syncthreads();
    }

    int elr = lane >> 2, elc = (lane & 3) * 2;
#pragma unroll
    for (int i = 0; i < 2; i++) {
        int x0 = wm + i * 16 + elr, x1 = x0 + 8;
#pragma unroll
        for (int jt = 0; jt < 4; jt++) {
            int col = coBase + wn + jt * 8 + elc;
            float b0 = __ldg(cbias + col), b1 = __ldg(cbias + col + 1);
            *(float2*)(outp + ((size_t)(y * 64 + x0)) * 256 + col) =
                make_float2(acc[i][jt][0] + b0, acc[i][jt][1] + b1);
            *(float2*)(outp + ((size_t)(y * 64 + x1)) * 256 + col) =
                make_float2(acc[i][jt][2] + b0, acc[i][jt][3] + b1);
        }
    }
}

// ---------------- launch ----------------
extern "C" void kernel_launch(void* const* d_in, const int* in_sizes, int n_in,
                              void* d_out, int out_size) {
    const float* z     = (const float*)d_in[0];
    const int*   ux    = (const int*)d_in[1];
    const int*   uy    = (const int*)d_in[2];
    const int*   ne    = (const int*)d_in[3];
    const float* ln1_s = (const float*)d_in[4];
    const float* ln1_b = (const float*)d_in[5];
    const float* W1    = (const float*)d_in[6];
    const float* b1    = (const float*)d_in[7];
    const float* ln2_s = (const float*)d_in[8];
    const float* ln2_b = (const float*)d_in[9];
    const float* W2    = (const float*)d_in[10];
    const float* b2    = (const float*)d_in[11];
    const float* ln3_s = (const float*)d_in[12];
    const float* ln3_b = (const float*)d_in[13];
    const float* cw    = (const float*)d_in[14];
    const float* cb    = (const float*)d_in[15];
    float* out = (float*)d_out;
    (void)in_sizes; (void)n_in; (void)out_size;

    cudaFuncSetAttribute(gemm_mma<0>, cudaFuncAttributeMaxDynamicSharedMemorySize, T_SMEM);
    cudaFuncSetAttribute(gemm_mma<1>, cudaFuncAttributeMaxDynamicSharedMemorySize, T_SMEM);
    cudaFuncSetAttribute(conv_mma,    cudaFuncAttributeMaxDynamicSharedMemorySize, T_SMEM);

    setup_kernel<<<4961, 256>>>(W1, W2, cw);
    compact_stats_kernel<<<U_, 128>>>(z, ne, ln1_s, ln1_b);
    gemm_mma<0><<<dim3(4, 512), 256, T_SMEM>>>(nullptr, nullptr, b1, nullptr, nullptr);
    gemm_mma<1><<<dim3(2, 512), 256, T_SMEM>>>(ln2_s, ln2_b, b2, ux, uy);
    ln3_kernel<<<4096, 256>>>(ln3_s, ln3_b);
    conv_mma<<<dim3(2, 64), 256, T_SMEM>>>(cb, out);
}